// round 10
// baseline (speedup 1.0000x reference)
#include <cuda_runtime.h>
#include <cstdint>
#include <cstddef>

// Problem constants
#define NB    4096
#define L2DIM 49
#define CDIM  128
#define BAD   324
#define CP    64            // channel pairs (f32x2)
#define NTHR  512

typedef unsigned long long ull;

__device__ __forceinline__ ull ffma2(ull a, ull b, ull c) {
    ull d;
    asm("fma.rn.f32x2 %0, %1, %2, %3;" : "=l"(d) : "l"(a), "l"(b), "l"(c));
    return d;
}
__device__ __forceinline__ ull fmul2(ull a, ull b) {
    ull d;
    asm("mul.rn.f32x2 %0, %1, %2;" : "=l"(d) : "l"(a), "l"(b));
    return d;
}
__device__ __forceinline__ ull fadd2(ull a, ull b) {
    ull d;
    asm("add.rn.f32x2 %0, %1, %2;" : "=l"(d) : "l"(a), "l"(b));
    return d;
}
__device__ __forceinline__ ull pack2(float x) {
    ull d;
    asm("mov.b64 %0, {%1, %1};" : "=l"(d) : "f"(x));
    return d;
}

// ---------------- SMEM layout ----------------
// [0, 165888)   G2s ull[324][64]  (squared grid; later overlaid by P with stride 66)
// [165888, ...) region2:
//   phase A: Bs ull[49*64] (25088 B) @ +0 ; As2 float[256*27] (27648 B) @ +25088
//   phase B: Ws float[132*64] (33792 B) @ +0
#define R2_OFF     165888
#define AS_OFF     (R2_OFF + 25088)
#define AS_STR     27          // floats per row (conflict-free: 8*27 mod 32 = 24)
#define WS_STR     64          // floats per (qq,b) row
#define P_STR      66          // ull stride for partials (kills STS conflicts)
#define SMEM_BYTES (AS_OFF + 27648 - 0)   // 218624

__global__ void __launch_bounds__(NTHR, 1)
fused_kernel(const float* __restrict__ X,
             const float* __restrict__ Wto,
             const float* __restrict__ Wf,
             float* __restrict__ Out) {
    extern __shared__ __align__(16) char smem[];
    ull*   G2s = reinterpret_cast<ull*>(smem);
    ull*   Bs  = reinterpret_cast<ull*>(smem + R2_OFF);
    float* As2 = reinterpret_cast<float*>(smem + AS_OFF);
    float* Ws  = reinterpret_cast<float*>(smem + R2_OFF);

    const int n    = blockIdx.x;
    const int tid  = threadIdx.x;
    const int wrp  = tid >> 5;
    const int lane = tid & 31;

    // Phase A roles: warp covers 16 rows x 64 cp; lane = (rg 0..1, cl 0..15)
    const int rg = lane >> 4;
    const int cl = lane & 15;

    // ---------- stage Bs: x[n] (float4 coalesced, conflict-free) ----------
    {
        const float4* Xv = reinterpret_cast<const float4*>(X + (size_t)n * L2DIM * CDIM);
        float4* Bv = reinterpret_cast<float4*>(Bs);
        for (int idx = tid; idx < L2DIM * 32; idx += NTHR) Bv[idx] = Xv[idx];
    }

    // ================= Phase A: G2s = (W_to @ x)^2 =================
    for (int chunk = 0; chunk < 2; chunk++) {
        const int  cbase  = chunk * 256;
        const int  nslots = chunk ? 5 : 16;
        const bool active = (wrp < nslots);
        const int  rbase  = wrp * 16 + rg * 8;    // local row base within chunk

        ull acc[8][4];
#pragma unroll
        for (int d = 0; d < 8; d++)
#pragma unroll
            for (int k = 0; k < 4; k++) acc[d][k] = 0ull;

#pragma unroll
        for (int ihalf = 0; ihalf < 2; ihalf++) {
            const int ioff = ihalf * 25;
            const int icnt = 25 - ihalf;          // 25 then 24
            __syncthreads();
            // stage As2[r][ii] = Wto[(cbase+r)][ioff+ii]  (coalesced LDG, conflict-free STS)
            for (int r = wrp; r < 256; r += 16) {
                if (lane < icnt) {
                    int grow = cbase + r;
                    float v = (grow < BAD) ? Wto[(size_t)grow * L2DIM + ioff + lane] : 0.0f;
                    As2[r * AS_STR + lane] = v;
                }
            }
            __syncthreads();

            if (active) {
                const float* wp = As2 + rbase * AS_STR;
                const ull*   xp = Bs + (size_t)ioff * CP + cl * 2;
#pragma unroll 5
                for (int ii = 0; ii < icnt; ii++) {
                    ull w[8];
#pragma unroll
                    for (int d = 0; d < 8; d++) w[d] = pack2(wp[d * AS_STR + ii]);
                    ulonglong2 xa = *reinterpret_cast<const ulonglong2*>(xp + (size_t)ii * CP);
                    ulonglong2 xb = *reinterpret_cast<const ulonglong2*>(xp + (size_t)ii * CP + 32);
#pragma unroll
                    for (int d = 0; d < 8; d++) {
                        acc[d][0] = ffma2(w[d], xa.x, acc[d][0]);
                        acc[d][1] = ffma2(w[d], xa.y, acc[d][1]);
                        acc[d][2] = ffma2(w[d], xb.x, acc[d][2]);
                        acc[d][3] = ffma2(w[d], xb.y, acc[d][3]);
                    }
                }
            }
        }

        // square & store (conflict-free: cl*2 contiguous within phase)
        if (active) {
#pragma unroll
            for (int d = 0; d < 8; d++) {
                int row = cbase + rbase + d;
                if (row < BAD) {
                    ulonglong2 v0, v1;
                    v0.x = fmul2(acc[d][0], acc[d][0]);
                    v0.y = fmul2(acc[d][1], acc[d][1]);
                    v1.x = fmul2(acc[d][2], acc[d][2]);
                    v1.y = fmul2(acc[d][3], acc[d][3]);
                    *reinterpret_cast<ulonglong2*>(G2s + (size_t)row * CP + cl * 2)      = v0;
                    *reinterpret_cast<ulonglong2*>(G2s + (size_t)row * CP + 32 + cl * 2) = v1;
                }
            }
        }
    }

    // ================= Phase B: out = W_from^T @ G2 =================
    // warp = (quarter q, cgroup cgw); lane<28 = (ig 0..6, clb 0..3)
    const int  q   = wrp >> 2;
    const int  cgw = wrp & 3;
    const int  ig  = lane >> 2;
    const int  clb = lane & 3;
    const bool act = (lane < 28);

    ull accB[7][4];
#pragma unroll
    for (int j = 0; j < 7; j++)
#pragma unroll
        for (int k = 0; k < 4; k++) accB[j][k] = 0ull;

    int off = 0;
    for (int round = 0; round < 3; round++) {
        const int csz = (round < 2) ? 33 : 15;
        __syncthreads();
        // stage Ws[(qq*33+b)][ig*8+j] = Wf[(qq*81+off+b)][ig*7+j]
        for (int rr = wrp; rr < 4 * csz; rr += 16) {
            int qq = rr / csz;
            int b  = rr - qq * csz;
            const float* src = Wf + (size_t)(qq * 81 + off + b) * L2DIM;
            float* dst = Ws + (qq * 33 + b) * WS_STR;
            {
                int i = lane;
                if (i < L2DIM) dst[(i / 7) * 8 + (i % 7)] = src[i];
                i = lane + 32;
                if (i < L2DIM) dst[(i / 7) * 8 + (i % 7)] = src[i];
            }
        }
        __syncthreads();

        if (act) {
            const float* wsq = Ws + (q * 33) * WS_STR + ig * 8;
            const ull*   gq  = G2s + (size_t)(q * 81 + off) * CP + cgw * 16 + clb * 4;
#pragma unroll 3
            for (int b = 0; b < csz; b++) {
                float2 wa = *reinterpret_cast<const float2*>(wsq + b * WS_STR);
                float2 wb = *reinterpret_cast<const float2*>(wsq + b * WS_STR + 2);
                float2 wc = *reinterpret_cast<const float2*>(wsq + b * WS_STR + 4);
                float  wd = wsq[b * WS_STR + 6];
                ull w0 = pack2(wa.x), w1 = pack2(wa.y), w2 = pack2(wb.x);
                ull w3 = pack2(wb.y), w4 = pack2(wc.x), w5 = pack2(wc.y);
                ull w6 = pack2(wd);
                ulonglong2 g01 = *reinterpret_cast<const ulonglong2*>(gq + (size_t)b * CP);
                ulonglong2 g23 = *reinterpret_cast<const ulonglong2*>(gq + (size_t)b * CP + 2);
                accB[0][0] = ffma2(w0, g01.x, accB[0][0]);
                accB[0][1] = ffma2(w0, g01.y, accB[0][1]);
                accB[0][2] = ffma2(w0, g23.x, accB[0][2]);
                accB[0][3] = ffma2(w0, g23.y, accB[0][3]);
                accB[1][0] = ffma2(w1, g01.x, accB[1][0]);
                accB[1][1] = ffma2(w1, g01.y, accB[1][1]);
                accB[1][2] = ffma2(w1, g23.x, accB[1][2]);
                accB[1][3] = ffma2(w1, g23.y, accB[1][3]);
                accB[2][0] = ffma2(w2, g01.x, accB[2][0]);
                accB[2][1] = ffma2(w2, g01.y, accB[2][1]);
                accB[2][2] = ffma2(w2, g23.x, accB[2][2]);
                accB[2][3] = ffma2(w2, g23.y, accB[2][3]);
                accB[3][0] = ffma2(w3, g01.x, accB[3][0]);
                accB[3][1] = ffma2(w3, g01.y, accB[3][1]);
                accB[3][2] = ffma2(w3, g23.x, accB[3][2]);
                accB[3][3] = ffma2(w3, g23.y, accB[3][3]);
                accB[4][0] = ffma2(w4, g01.x, accB[4][0]);
                accB[4][1] = ffma2(w4, g01.y, accB[4][1]);
                accB[4][2] = ffma2(w4, g23.x, accB[4][2]);
                accB[4][3] = ffma2(w4, g23.y, accB[4][3]);
                accB[5][0] = ffma2(w5, g01.x, accB[5][0]);
                accB[5][1] = ffma2(w5, g01.y, accB[5][1]);
                accB[5][2] = ffma2(w5, g23.x, accB[5][2]);
                accB[5][3] = ffma2(w5, g23.y, accB[5][3]);
                accB[6][0] = ffma2(w6, g01.x, accB[6][0]);
                accB[6][1] = ffma2(w6, g01.y, accB[6][1]);
                accB[6][2] = ffma2(w6, g23.x, accB[6][2]);
                accB[6][3] = ffma2(w6, g23.y, accB[6][3]);
            }
        }
        off += csz;
    }

    // ---------- Phase C: 4-way quarter reduction + writeout ----------
    __syncthreads();   // all G2s reads done; overlay P (stride 66, conflict-free)
    ull* P = G2s;
    if (act) {
#pragma unroll
        for (int j = 0; j < 7; j++) {
            int i = ig * 7 + j;
            ulonglong2 a01, a23;
            a01.x = accB[j][0]; a01.y = accB[j][1];
            a23.x = accB[j][2]; a23.y = accB[j][3];
            ull* pb = P + (size_t)(q * L2DIM + i) * P_STR + cgw * 16 + clb * 4;
            *reinterpret_cast<ulonglong2*>(pb)     = a01;
            *reinterpret_cast<ulonglong2*>(pb + 2) = a23;
        }
    }
    __syncthreads();
    ull* outp = reinterpret_cast<ull*>(Out) + (size_t)n * L2DIM * CP;
    for (int idx = tid; idx < L2DIM * CP; idx += NTHR) {
        int i = idx >> 6;
        int c = idx & 63;
        ull s = fadd2(
            fadd2(P[(size_t)i * P_STR + c],
                  P[(size_t)(L2DIM + i) * P_STR + c]),
            fadd2(P[(size_t)(2 * L2DIM + i) * P_STR + c],
                  P[(size_t)(3 * L2DIM + i) * P_STR + c]));
        outp[idx] = s;
    }
}

// ---------------- launcher ----------------
extern "C" void kernel_launch(void* const* d_in, const int* in_sizes, int n_in,
                              void* d_out, int out_size) {
    const float* X   = (const float*)d_in[0];  // inputs  (N, 49, 128)
    const float* Wto = (const float*)d_in[1];  // W_to    (18, 18, 49)
    const float* Wf  = (const float*)d_in[2];  // W_from  (18, 18, 49)
    float* Out = (float*)d_out;                // (N, 49, 128)

    static bool attr_set = false;
    if (!attr_set) {
        cudaFuncSetAttribute(fused_kernel,
                             cudaFuncAttributeMaxDynamicSharedMemorySize,
                             SMEM_BYTES);
        attr_set = true;
    }

    fused_kernel<<<NB, NTHR, SMEM_BYTES>>>(X, Wto, Wf, Out);
}

// round 11
// speedup vs baseline: 1.7814x; 1.7814x over previous
#include <cuda_runtime.h>
#include <cuda_bf16.h>
#include <cstdint>
#include <cstddef>

// Problem constants
#define NB    4096
#define L2DIM 49
#define CDIM  128
#define BAD   324
#define MPAD  336     // ba padded to 21 x 16 (GEMM1 M)
#define KPAD  64      // i padded (GEMM1 K)
#define IPAD  64      // i padded (GEMM2 M)
#define KBA   384     // ba padded (WfT row length, 48 x 16B chunks)
#define NTHR  512
#define CHUNK 112

typedef uint32_t u32;

// Bank swizzle: permute 16B chunks within a row; rows r and r+8 map differently
// in the low 3 bits so ldmatrix x4 half-tiles never collide.
__device__ __forceinline__ int swz(int row, int chunk) {
    return chunk ^ ((row + (row >> 3)) & 7);
}

// ---------------- device globals: pre-split, pre-swizzled weights ----------------
__device__ __nv_bfloat16 g_WtoH[MPAD * 64];    // [ba][i] rows 128B
__device__ __nv_bfloat16 g_WtoL[MPAD * 64];
__device__ __nv_bfloat16 g_WfTH[IPAD * KBA];   // [i][ba] rows 768B
__device__ __nv_bfloat16 g_WfTL[IPAD * KBA];

__global__ void prep_kernel(const float* __restrict__ Wto,
                            const float* __restrict__ Wf) {
    int idx = blockIdx.x * blockDim.x + threadIdx.x;
    if (idx < MPAD * 64) {
        int row = idx >> 6, col = idx & 63;
        float w = (row < BAD && col < L2DIM) ? Wto[row * L2DIM + col] : 0.0f;
        __nv_bfloat16 h = __float2bfloat16(w);
        __nv_bfloat16 l = __float2bfloat16(w - __bfloat162float(h));
        int pos = row * 64 + swz(row, col >> 3) * 8 + (col & 7);
        g_WtoH[pos] = h;
        g_WtoL[pos] = l;
    }
    int idx2 = idx - MPAD * 64;
    if (idx2 >= 0 && idx2 < IPAD * KBA) {
        int row = idx2 / KBA, col = idx2 - row * KBA;  // row = i, col = ba
        float w = (row < L2DIM && col < BAD) ? Wf[col * L2DIM + row] : 0.0f;
        __nv_bfloat16 h = __float2bfloat16(w);
        __nv_bfloat16 l = __float2bfloat16(w - __bfloat162float(h));
        int pos = row * KBA + swz(row, col >> 3) * 8 + (col & 7);
        g_WfTH[pos] = h;
        g_WfTL[pos] = l;
    }
}

// ---------------- mma / ldmatrix wrappers ----------------
__device__ __forceinline__ void mma16816(float* d, uint4 a, u32 b0, u32 b1) {
    asm volatile(
        "mma.sync.aligned.m16n8k16.row.col.f32.bf16.bf16.f32 "
        "{%0,%1,%2,%3}, {%4,%5,%6,%7}, {%8,%9}, {%0,%1,%2,%3};"
        : "+f"(d[0]), "+f"(d[1]), "+f"(d[2]), "+f"(d[3])
        : "r"(a.x), "r"(a.y), "r"(a.z), "r"(a.w), "r"(b0), "r"(b1));
}
__device__ __forceinline__ uint4 ldsm4(u32 addr) {
    uint4 r;
    asm volatile("ldmatrix.sync.aligned.m8n8.x4.shared.b16 {%0,%1,%2,%3}, [%4];"
                 : "=r"(r.x), "=r"(r.y), "=r"(r.z), "=r"(r.w) : "r"(addr));
    return r;
}
__device__ __forceinline__ uint4 ldsm4t(u32 addr) {
    uint4 r;
    asm volatile("ldmatrix.sync.aligned.m8n8.x4.trans.shared.b16 {%0,%1,%2,%3}, [%4];"
                 : "=r"(r.x), "=r"(r.y), "=r"(r.z), "=r"(r.w) : "r"(addr));
    return r;
}
__device__ __forceinline__ u32 pkbf(float a, float b) {
    __nv_bfloat162 t = __floats2bfloat162_rn(a, b);
    u32 r;
    memcpy(&r, &t, 4);
    return r;
}

// ---------------- SMEM layout (byte offsets), total 217088 ----------------
#define XS_H   0        // [64][128] bf16 rows 256B  (16384)
#define XS_L   16384
#define WTS_H  32768    // [112][64] bf16 rows 128B  (14336)
#define WTS_L  47104
#define G2_H   61440    // [112][128] bf16 rows 256B (28672)
#define G2_L   90112
#define WFT_H  118784   // [64][384] bf16 rows 768B  (49152)
#define WFT_L  167936
#define SMEM_BYTES 217088

__global__ void __launch_bounds__(NTHR, 1)
fused_kernel(const float* __restrict__ X, float* __restrict__ Out) {
    extern __shared__ __align__(16) char smem[];
    u32 smem_u32;
    asm("{ .reg .u64 t; cvta.to.shared.u64 t, %1; cvt.u32.u64 %0, t; }"
        : "=r"(smem_u32) : "l"(smem));

    const int n    = blockIdx.x;
    const int tid  = threadIdx.x;
    const int wrp  = tid >> 5;
    const int lane = tid & 31;
    const int gg   = lane >> 2;   // mma fragment row group
    const int tc   = lane & 3;    // mma fragment col/thread-in-group

    // ---------- stage X[n] split (hi/lo) + zero pad, and WfT copy ----------
    {
        const float2* X2 = reinterpret_cast<const float2*>(X + (size_t)n * L2DIM * CDIM);
        u32* xh = reinterpret_cast<u32*>(smem + XS_H);
        u32* xl = reinterpret_cast<u32*>(smem + XS_L);
        for (int p = tid; p < L2DIM * 64; p += NTHR) {
            int i = p >> 6, cp = p & 63;
            float2 v = X2[p];
            __nv_bfloat16 h0 = __float2bfloat16(v.x);
            __nv_bfloat16 h1 = __float2bfloat16(v.y);
            float r0 = v.x - __bfloat162float(h0);
            float r1 = v.y - __bfloat162float(h1);
            int uidx = i * 64 + swz(i, cp >> 2) * 4 + (cp & 3);
            xh[uidx] = pkbf(__bfloat162float(h0), __bfloat162float(h1));
            xl[uidx] = pkbf(r0, r1);
        }
        for (int p = tid; p < (KPAD - L2DIM) * 64; p += NTHR) {
            int i = L2DIM + p / 64, c = p % 64;
            xh[i * 64 + c] = 0u;
            xl[i * 64 + c] = 0u;
        }
        uint4* sh = reinterpret_cast<uint4*>(smem + WFT_H);
        uint4* sl = reinterpret_cast<uint4*>(smem + WFT_L);
        const uint4* gh = reinterpret_cast<const uint4*>(g_WfTH);
        const uint4* gl = reinterpret_cast<const uint4*>(g_WfTL);
        for (int p = tid; p < IPAD * KBA * 2 / 16; p += NTHR) {
            sh[p] = gh[p];
            sl[p] = gl[p];
        }
    }

    // GEMM2 output accumulators (live across chunks)
    float d2[4][4];
#pragma unroll
    for (int a = 0; a < 4; a++)
#pragma unroll
        for (int b = 0; b < 4; b++) d2[a][b] = 0.0f;

    const int mtw = wrp >> 2;   // GEMM2: i-tile (rows mtw*16..+15)
    const int ntw = wrp & 3;    // GEMM2: c-group (cols ntw*32..+31)

    for (int ch = 0; ch < 3; ch++) {
        const int cbase = ch * CHUNK;
        __syncthreads();   // prev GEMM2 reads done before restage/epilogue
        // stage Wto chunk (raw copy; swizzle already applied with global rows)
        {
            uint4* sh = reinterpret_cast<uint4*>(smem + WTS_H);
            uint4* sl = reinterpret_cast<uint4*>(smem + WTS_L);
            const uint4* gh = reinterpret_cast<const uint4*>(g_WtoH) + cbase * 8;
            const uint4* gl = reinterpret_cast<const uint4*>(g_WtoL) + cbase * 8;
            for (int p = tid; p < CHUNK * 8; p += NTHR) {
                sh[p] = gh[p];
                sl[p] = gl[p];
            }
        }
        __syncthreads();

        // ---------------- GEMM1: D1[ba_local 112][c 128] ----------------
        if (wrp < 14) {
            const int mt = wrp >> 1;   // 0..6: rows mt*16..+15
            const int nt = wrp & 1;    // cols nt*64..+63
            float d1[8][4];
#pragma unroll
            for (int a = 0; a < 8; a++)
#pragma unroll
                for (int b = 0; b < 4; b++) d1[a][b] = 0.0f;

#pragma unroll
            for (int pass = 0; pass < 3; pass++) {
                const u32 abase = smem_u32 + (pass == 2 ? WTS_L : WTS_H);
                const u32 bbase = smem_u32 + (pass == 1 ? XS_L : XS_H);
#pragma unroll
                for (int ks = 0; ks < 4; ks++) {
                    int arow = mt * 16 + ((lane >> 3) & 1) * 8 + (lane & 7);
                    int achk = ks * 2 + (lane >> 4);
                    uint4 A = ldsm4(abase + arow * 128 + swz(cbase + arow, achk) * 16);
                    int krow = ks * 16 + ((lane >> 3) & 1) * 8 + (lane & 7);
#pragma unroll
                    for (int j = 0; j < 4; j++) {
                        int nchk = nt * 8 + j * 2 + (lane >> 4);
                        uint4 B = ldsm4t(bbase + krow * 256 + swz(krow, nchk) * 16);
                        mma16816(d1[2 * j],     A, B.x, B.y);
                        mma16816(d1[2 * j + 1], A, B.z, B.w);
                    }
                }
            }
            // epilogue: square, split hi/lo, store G2 (swizzled)
            u32* g2h = reinterpret_cast<u32*>(smem + G2_H);
            u32* g2l = reinterpret_cast<u32*>(smem + G2_L);
#pragma unroll
            for (int nn = 0; nn < 8; nn++) {
                int chk = nt * 8 + nn;
#pragma unroll
                for (int hr = 0; hr < 2; hr++) {
                    int row = mt * 16 + gg + hr * 8;
                    float s0 = d1[nn][hr * 2 + 0]; s0 *= s0;
                    float s1 = d1[nn][hr * 2 + 1]; s1 *= s1;
                    __nv_bfloat16 h0 = __float2bfloat16(s0);
                    __nv_bfloat16 h1 = __float2bfloat16(s1);
                    float r0 = s0 - __bfloat162float(h0);
                    float r1 = s1 - __bfloat162float(h1);
                    int uidx = row * 64 + swz(row, chk) * 4 + tc;
                    g2h[uidx] = pkbf(__bfloat162float(h0), __bfloat162float(h1));
                    g2l[uidx] = pkbf(r0, r1);
                }
            }
        }
        __syncthreads();

        // ---------------- GEMM2 partial: accumulate over this chunk's 112 ba ----------------
#pragma unroll
        for (int pass = 0; pass < 3; pass++) {
            const u32 abase = smem_u32 + (pass == 2 ? WFT_L : WFT_H);
            const u32 bbase = smem_u32 + (pass == 1 ? G2_L : G2_H);
#pragma unroll
            for (int ks = 0; ks < 7; ks++) {
                int arow = mtw * 16 + ((lane >> 3) & 1) * 8 + (lane & 7);
                int achk = cbase / 8 + ks * 2 + (lane >> 4);
                uint4 A = ldsm4(abase + arow * 768 + swz(arow, achk) * 16);
                int krow = ks * 16 + ((lane >> 3) & 1) * 8 + (lane & 7);
#pragma unroll
                for (int j = 0; j < 2; j++) {
                    int nchk = ntw * 4 + j * 2 + (lane >> 4);
                    uint4 B = ldsm4t(bbase + krow * 256 + swz(krow, nchk) * 16);
                    mma16816(d2[2 * j],     A, B.x, B.y);
                    mma16816(d2[2 * j + 1], A, B.z, B.w);
                }
            }
        }
    }

    // ---------------- writeout: D2[i][c] fp32 ----------------
    float2* O2 = reinterpret_cast<float2*>(Out + (size_t)n * L2DIM * CDIM);
#pragma unroll
    for (int nf = 0; nf < 4; nf++) {
        int c  = ntw * 32 + nf * 8 + tc * 2;
        int i0 = mtw * 16 + gg;
        if (i0 < L2DIM) O2[i0 * 64 + (c >> 1)] = make_float2(d2[nf][0], d2[nf][1]);
        int i1 = i0 + 8;
        if (i1 < L2DIM) O2[i1 * 64 + (c >> 1)] = make_float2(d2[nf][2], d2[nf][3]);
    }
}

// ---------------- launcher ----------------
extern "C" void kernel_launch(void* const* d_in, const int* in_sizes, int n_in,
                              void* d_out, int out_size) {
    const float* X   = (const float*)d_in[0];  // inputs  (N, 49, 128)
    const float* Wto = (const float*)d_in[1];  // W_to    (18, 18, 49)
    const float* Wf  = (const float*)d_in[2];  // W_from  (18, 18, 49)
    float* Out = (float*)d_out;                // (N, 49, 128)

    static bool attr_set = false;
    if (!attr_set) {
        cudaFuncSetAttribute(fused_kernel,
                             cudaFuncAttributeMaxDynamicSharedMemorySize,
                             SMEM_BYTES);
        attr_set = true;
    }

    int prep_total = MPAD * 64 + IPAD * KBA;   // 46080
    prep_kernel<<<(prep_total + 255) / 256, 256>>>(Wto, Wf);

    fused_kernel<<<NB, NTHR, SMEM_BYTES>>>(X, Out);
}